// round 11
// baseline (speedup 1.0000x reference)
#include <cuda_runtime.h>
#include <cuda_fp16.h>
#include <math.h>
#include <float.h>
#include <stdint.h>

#define Bb  8
#define Cc  256
#define HH  160
#define WW  160
#define HDs 40
#define WDs 40
#define NT  1600
#define MT  (Bb*NT)
#define SA  40              // smem row stride (halves) for [r][k] GEMM tiles
#define ASW (64*SA)
#define BSW 5120
#define SQ  264             // smem row stride for Q/K/V tiles (256+8)
#define SP  72              // smem row stride for P tile (64+8)
#define NCH 25              // kv chunks of 64
// fattn smem layout (halves)
#define OFF_Q 0
#define OFF_K (32*SQ)                 // 8448
#define OFF_V (OFF_K + 64*SQ)         // 25344
#define OFF_P (OFF_V + 64*SQ)         // 42240
#define FATTN_HALVES (OFF_P + 32*SP)  // 44544
#define FATTN_SMEM (FATTN_HALVES*2 + 96*4)   // + rpart[64], rinv[32] floats

// ---------------- static scratch ----------------
__device__ __align__(256) __half g_ds_rgb[(size_t)Bb*NT*Cc];     // token-major [b][n][c]
__device__ __align__(256) __half g_ds_ir [(size_t)Bb*NT*Cc];
__device__ __align__(256) __half g_tok[6][(size_t)MT*Cc];        // [b*NT+n][c]
__device__ __align__(256) __half g_zcat[(size_t)MT*2*Cc];        // [b*NT+n][2C]
__device__ __align__(256) __half g_wh[655360];                   // fp16 weights
__device__ float g_pre[3][(size_t)MT*Cc];
__device__ float g_fused[(size_t)Bb*Cc*NT];

__device__ __forceinline__ void cpa16u(uint32_t smem_dst, const void* gsrc) {
    asm volatile("cp.async.cg.shared.global [%0], [%1], 16;" :: "r"(smem_dst), "l"(gsrc));
}
__device__ __forceinline__ void ldsm_x4u(unsigned* r, uint32_t s) {
    asm volatile("ldmatrix.sync.aligned.m8n8.x4.shared.b16 {%0,%1,%2,%3}, [%4];"
                 : "=r"(r[0]), "=r"(r[1]), "=r"(r[2]), "=r"(r[3]) : "r"(s));
}
__device__ __forceinline__ void ldsm_x4tu(unsigned* r, uint32_t s) {
    asm volatile("ldmatrix.sync.aligned.m8n8.x4.trans.shared.b16 {%0,%1,%2,%3}, [%4];"
                 : "=r"(r[0]), "=r"(r[1]), "=r"(r[2]), "=r"(r[3]) : "r"(s));
}
__device__ __forceinline__ void hmma(float* d, const unsigned* a, unsigned b0, unsigned b1) {
    asm volatile("mma.sync.aligned.m16n8k16.row.col.f32.f16.f16.f32 "
                 "{%0,%1,%2,%3}, {%4,%5,%6,%7}, {%8,%9}, {%0,%1,%2,%3};"
                 : "+f"(d[0]), "+f"(d[1]), "+f"(d[2]), "+f"(d[3])
                 : "r"(a[0]), "r"(a[1]), "r"(a[2]), "r"(a[3]), "r"(b0), "r"(b1));
}

// ======== fp16 GEMM core (proj/final): 64x128 block, 128 thr, 3-stage ========
__device__ __forceinline__ void gemm64_fp16(
    const __half* __restrict__ A, int lda,
    const __half* __restrict__ B, int ldb,
    int K, float acc[2][8][4])
{
    __shared__ __align__(16) __half As[3][ASW];
    __shared__ __align__(16) __half Bs[3][BSW];
    const int tid = threadIdx.x, lane = tid & 31, warp = tid >> 5;
    const int wm = (warp >> 1) * 32, wn = (warp & 1) * 64;

    const int a_row = tid >> 2, a_kg = (tid & 3) * 8;
    const uint32_t as_b = (uint32_t)__cvta_generic_to_shared(&As[0][0]);
    const uint32_t bs_b = (uint32_t)__cvta_generic_to_shared(&Bs[0][0]);
    const uint32_t a_d0 = as_b + 2 * (a_row * SA + a_kg);
    const uint32_t a_d1 = a_d0 + 2 * (32 * SA);
    const uint32_t b_d0 = bs_b + 2 * (a_row * SA + a_kg);
    const uint32_t b_d1 = b_d0 + 2 * (32 * SA);
    const uint32_t b_d2 = b_d0 + 2 * (64 * SA);
    const uint32_t b_d3 = b_d0 + 2 * (96 * SA);

    auto issue = [&](int ci) {
        int k0 = ci * 32;
        uint32_t ao = (ci % 3) * (ASW * 2), bo = (ci % 3) * (BSW * 2);
        cpa16u(a_d0 + ao, A + (size_t)a_row * lda + k0 + a_kg);
        cpa16u(a_d1 + ao, A + (size_t)(a_row + 32) * lda + k0 + a_kg);
        const __half* gb = B + (size_t)a_row * ldb + k0 + a_kg;
        cpa16u(b_d0 + bo, gb);
        cpa16u(b_d1 + bo, gb + (size_t)32 * ldb);
        cpa16u(b_d2 + bo, gb + (size_t)64 * ldb);
        cpa16u(b_d3 + bo, gb + (size_t)96 * ldb);
        asm volatile("cp.async.commit_group;");
    };

    const uint32_t a_f0 = as_b + 2 * ((wm + (lane & 15)) * SA + (lane >> 4) * 8);
    const uint32_t a_f1 = a_f0 + 2 * (16 * SA);
    uint32_t b_f[4];
    {
        uint32_t base = bs_b + 2 * ((wn + (lane & 15)) * SA + (lane >> 4) * 8);
#pragma unroll
        for (int gi = 0; gi < 4; gi++) b_f[gi] = base + 2 * (gi * 16 * SA);
    }

    const int nk = K / 32;
    issue(0);
    if (nk > 1) issue(1);
    for (int i = 0; i < nk; i++) {
        if (i + 1 < nk) asm volatile("cp.async.wait_group 1;");
        else            asm volatile("cp.async.wait_group 0;");
        __syncthreads();
        if (i + 2 < nk) issue(i + 2);
        const uint32_t ao = (i % 3) * (ASW * 2), bo = (i % 3) * (BSW * 2);
#pragma unroll
        for (int s = 0; s < 2; s++) {
            const int kk = s * 16;
            unsigned a[2][4], bf[4][4];
            ldsm_x4u(a[0], a_f0 + ao + 2 * kk);
            ldsm_x4u(a[1], a_f1 + ao + 2 * kk);
#pragma unroll
            for (int gi = 0; gi < 4; gi++) ldsm_x4u(bf[gi], b_f[gi] + bo + 2 * kk);
#pragma unroll
            for (int mi = 0; mi < 2; mi++)
#pragma unroll
                for (int ni = 0; ni < 8; ni++) {
                    int gi = ni >> 1, hi = ni & 1;
                    hmma(acc[mi][ni], a[mi], bf[gi][hi], bf[gi][hi + 2]);
                }
        }
    }
}

// ---------------- weight prep ----------------
__global__ void wprep_kernel(
    const float* w0, const float* w1, const float* w2, const float* w3,
    const float* w4, const float* w5, const float* w6, const float* w7, const float* w8)
{
    int seg = blockIdx.y;
    int idx = blockIdx.x * 256 + threadIdx.x;
    int size = (seg == 8) ? 131072 : 65536;
    if (idx >= size) return;
    const float* src;
    switch (seg) {
        case 0: src = w0; break; case 1: src = w1; break; case 2: src = w2; break;
        case 3: src = w3; break; case 4: src = w4; break; case 5: src = w5; break;
        case 6: src = w6; break; case 7: src = w7; break; default: src = w8; break;
    }
    g_wh[seg * 65536 + idx] = __float2half_rn(src[idx]);
}

// ---------------- downsample: 2x2 mean -> token-major fp16 [b][n][c] ----------------
__global__ void ds_kernel(const float* __restrict__ zr, const float* __restrict__ zi) {
    __shared__ float t[32][33];
    int b = blockIdx.z, n0 = blockIdx.x * 32, c0 = blockIdx.y * 32;
    int tx = threadIdx.x, ty = threadIdx.y;
#pragma unroll
    for (int m = 0; m < 2; m++) {
        const float* src = m ? zi : zr;
        __half* dst = m ? g_ds_ir : g_ds_rgb;
        if (m) __syncthreads();
#pragma unroll
        for (int i = 0; i < 4; i++) {
            int n = n0 + tx, c = c0 + ty + 8 * i;
            int ho = n / WDs, wo = n % WDs;
            const float* p = src + ((size_t)(b * Cc + c) * HH + 4 * ho + 1) * WW + 4 * wo + 1;
            t[tx][ty + 8 * i] = 0.25f * (p[0] + p[1] + p[WW] + p[WW + 1]);
        }
        __syncthreads();
#pragma unroll
        for (int i = 0; i < 4; i++) {
            int n = n0 + ty + 8 * i, c = c0 + tx;
            dst[((size_t)b * NT + n) * Cc + c] = __float2half_rn(t[ty + 8 * i][tx]);
        }
    }
}

// ---------------- projections ----------------
__global__ void __launch_bounds__(128) proj_gemm(
    const float* __restrict__ bq_rgb, const float* __restrict__ bk_ir,
    const float* __restrict__ bv_ir,  const float* __restrict__ bq_ir,
    const float* __restrict__ bk_rgb, const float* __restrict__ bv_rgb)
{
    int b = blockIdx.x / 25, mloc = (blockIdx.x % 25) * 64;
    int n0 = blockIdx.y * 128, p = blockIdx.z;
    const __half* Ain = (p == 0 || p == 4 || p == 5) ? g_ds_rgb : g_ds_ir;
    const float* bias;
    switch (p) {
        case 0: bias = bq_rgb; break; case 1: bias = bk_ir;  break;
        case 2: bias = bv_ir;  break; case 3: bias = bq_ir;  break;
        case 4: bias = bk_rgb; break; default: bias = bv_rgb; break;
    }
    const __half* A = Ain + ((size_t)b * NT + mloc) * Cc;
    const __half* W = g_wh + p * 65536 + (size_t)n0 * Cc;
    float acc[2][8][4] = {};
    gemm64_fp16(A, Cc, W, Cc, Cc, acc);

    const int tid = threadIdx.x, lane = tid & 31, warp = tid >> 5;
    const int wm = (warp >> 1) * 32, wn = (warp & 1) * 64;
    const int g = lane >> 2, tg = lane & 3;
    __half* out = g_tok[p] + ((size_t)b * NT + mloc) * Cc + n0;
#pragma unroll
    for (int mi = 0; mi < 2; mi++) {
        int r0 = wm + mi * 16 + g;
#pragma unroll
        for (int ni = 0; ni < 8; ni++) {
            int col = wn + ni * 8 + 2 * tg;
            float b0 = bias[n0 + col], b1 = bias[n0 + col + 1];
            *(__half2*)(out + (size_t)r0 * Cc + col) =
                __floats2half2_rn(acc[mi][ni][0] + b0, acc[mi][ni][1] + b1);
            *(__half2*)(out + (size_t)(r0 + 8) * Cc + col) =
                __floats2half2_rn(acc[mi][ni][2] + b0, acc[mi][ni][3] + b1);
        }
    }
}

// ======== fused attention: S=QK^T/16, exp, rowsum, O=P@V, normalize -> zcat ========
// grid (50, 16): 32 query rows per CTA, 128 threads (4 warps).
__global__ void __launch_bounds__(128) fattn_kernel() {
    extern __shared__ __half sh[];
    float* rpart = (float*)(sh + FATTN_HALVES);   // [2][32]
    float* rinv  = rpart + 64;                    // [32]

    const int m0 = blockIdx.x * 32;
    const int z = blockIdx.y, dir = z >> 3, b = z & 7;
    const __half* Qg = g_tok[dir ? 3 : 0] + ((size_t)b * NT + m0) * Cc;
    const __half* Kg = g_tok[dir ? 4 : 1] + (size_t)b * NT * Cc;
    const __half* Vg = g_tok[dir ? 5 : 2] + (size_t)b * NT * Cc;

    const int tid = threadIdx.x, lane = tid & 31, warp = tid >> 5;
    const int wm2 = warp >> 1, wn2 = warp & 1;     // S-phase tiling 2x2
    const int g = lane >> 2, tg = lane & 3;

    const uint32_t shb = (uint32_t)__cvta_generic_to_shared(sh);
    const uint32_t qb = shb, kb = shb + OFF_K * 2, vb = shb + OFF_V * 2, pb = shb + OFF_P * 2;

    // cp.async geometry: row = idx>>5, chunk16B = idx&31
    const int l_row = tid >> 5 << 2;   // unused helper suppressed
    auto issue_K = [&](int c) {
        int t0 = c * 64;
#pragma unroll
        for (int i = 0; i < 16; i++) {
            int idx = tid + i * 128;
            int row = idx >> 5, ch = idx & 31;
            cpa16u(kb + 2 * (row * SQ + ch * 8), Kg + (size_t)(t0 + row) * Cc + ch * 8);
        }
        asm volatile("cp.async.commit_group;");
    };
    auto issue_V = [&](int c) {
        int t0 = c * 64;
#pragma unroll
        for (int i = 0; i < 16; i++) {
            int idx = tid + i * 128;
            int row = idx >> 5, ch = idx & 31;
            cpa16u(vb + 2 * (row * SQ + ch * 8), Vg + (size_t)(t0 + row) * Cc + ch * 8);
        }
        asm volatile("cp.async.commit_group;");
    };

    // prologue: Q + K0 in one group, V0 in the next
    {
#pragma unroll
        for (int i = 0; i < 8; i++) {
            int idx = tid + i * 128;
            int row = idx >> 5, ch = idx & 31;
            cpa16u(qb + 2 * (row * SQ + ch * 8), Qg + (size_t)row * Cc + ch * 8);
        }
        issue_K(0);   // commits Q+K0 together
        issue_V(0);
    }

    // hoisted ldsm addresses
    const uint32_t qa = qb + 2 * ((wm2 * 16 + (lane & 15)) * SQ + (lane >> 4) * 8);
    const uint32_t ka0 = kb + 2 * ((wn2 * 32 + (lane & 15)) * SQ + (lane >> 4) * 8);
    const uint32_t ka1 = ka0 + 2 * (16 * SQ);
    const uint32_t pa0 = pb + 2 * (((lane & 15)) * SP + (lane >> 4) * 8);
    const uint32_t pa1 = pa0 + 2 * (16 * SP);
    uint32_t va[4];
#pragma unroll
    for (int gi = 0; gi < 4; gi++)
        va[gi] = vb + 2 * (((lane & 7) + 8 * (lane >> 4)) * SQ
                           + warp * 64 + gi * 16 + 8 * ((lane >> 3) & 1));

    float o[2][8][4] = {};
    float rs0 = 0.f, rs1 = 0.f;

    for (int c = 0; c < NCH; c++) {
        // ---- wait K_c (Q included in its group), compute S ----
        asm volatile("cp.async.wait_group 1;");
        __syncthreads();
        float s[2][2][4] = {};    // [bi n16][ni n8][4]
#pragma unroll
        for (int ks = 0; ks < 16; ks++) {
            const uint32_t ko = 2 * (ks * 16);
            unsigned aq[4], bk0[4], bk1[4];
            ldsm_x4u(aq, qa + ko);
            ldsm_x4u(bk0, ka0 + ko);
            ldsm_x4u(bk1, ka1 + ko);
            hmma(s[0][0], aq, bk0[0], bk0[2]);
            hmma(s[0][1], aq, bk0[1], bk0[3]);
            hmma(s[1][0], aq, bk1[0], bk1[2]);
            hmma(s[1][1], aq, bk1[1], bk1[3]);
        }
        // ---- exp, rowsum partials, store P (fp16) ----
        {
            int r0 = wm2 * 16 + g;
            float p0 = 0.f, p1 = 0.f;
#pragma unroll
            for (int bi = 0; bi < 2; bi++)
#pragma unroll
                for (int ni = 0; ni < 2; ni++) {
                    int col = wn2 * 32 + bi * 16 + ni * 8 + 2 * tg;
                    float e0 = __expf(s[bi][ni][0] * 0.0625f);
                    float e1 = __expf(s[bi][ni][1] * 0.0625f);
                    float e2 = __expf(s[bi][ni][2] * 0.0625f);
                    float e3 = __expf(s[bi][ni][3] * 0.0625f);
                    *(__half2*)&sh[OFF_P + r0 * SP + col] = __floats2half2_rn(e0, e1);
                    *(__half2*)&sh[OFF_P + (r0 + 8) * SP + col] = __floats2half2_rn(e2, e3);
                    p0 += e0 + e1;
                    p1 += e2 + e3;
                }
            rs0 += p0;
            rs1 += p1;
        }
        __syncthreads();          // P complete; K_c reads done
        if (c + 1 < NCH) issue_K(c + 1);
        // ---- wait V_c, compute O += P @ V ----
        if (c + 1 < NCH) asm volatile("cp.async.wait_group 1;");
        else             asm volatile("cp.async.wait_group 0;");
        __syncthreads();
#pragma unroll
        for (int ks = 0; ks < 4; ks++) {
            unsigned ap[2][4], bv[4][4];
            ldsm_x4u(ap[0], pa0 + 2 * (ks * 16));
            ldsm_x4u(ap[1], pa1 + 2 * (ks * 16));
#pragma unroll
            for (int gi = 0; gi < 4; gi++) ldsm_x4tu(bv[gi], va[gi] + 2 * (ks * 16 * SQ));
#pragma unroll
            for (int mi = 0; mi < 2; mi++)
#pragma unroll
                for (int ni = 0; ni < 8; ni++) {
                    int gi = ni >> 1, hi = ni & 1;
                    hmma(o[mi][ni], ap[mi], bv[gi][hi], bv[gi][hi + 2]);
                }
        }
        __syncthreads();          // V_c reads done
        if (c + 1 < NCH) issue_V(c + 1);
    }

    // ---- deterministic rowsum reduce ----
    rs0 += __shfl_xor_sync(0xffffffffu, rs0, 1); rs0 += __shfl_xor_sync(0xffffffffu, rs0, 2);
    rs1 += __shfl_xor_sync(0xffffffffu, rs1, 1); rs1 += __shfl_xor_sync(0xffffffffu, rs1, 2);
    if (tg == 0) {
        rpart[wn2 * 32 + wm2 * 16 + g] = rs0;
        rpart[wn2 * 32 + wm2 * 16 + 8 + g] = rs1;
    }
    __syncthreads();
    if (tid < 32) rinv[tid] = 1.0f / (rpart[tid] + rpart[32 + tid]);
    __syncthreads();

    // ---- normalize + store O: warp owns cols warp*64..+64, rows 0..31 ----
    __half* out = g_zcat + ((size_t)b * NT + m0) * 2 * Cc + dir * Cc + warp * 64;
#pragma unroll
    for (int mi = 0; mi < 2; mi++) {
        int r0 = mi * 16 + g;
        float i0 = rinv[r0], i1 = rinv[r0 + 8];
#pragma unroll
        for (int ni = 0; ni < 8; ni++) {
            int col = ni * 8 + 2 * tg;
            *(__half2*)(out + (size_t)r0 * 2 * Cc + col) =
                __floats2half2_rn(o[mi][ni][0] * i0, o[mi][ni][1] * i0);
            *(__half2*)(out + (size_t)(r0 + 8) * 2 * Cc + col) =
                __floats2half2_rn(o[mi][ni][2] * i1, o[mi][ni][3] * i1);
        }
    }
}

// ---------------- epilogue GEMMs -> fp32 pre-activations ----------------
__global__ void __launch_bounds__(128) final_gemm(
    const float* __restrict__ brgb, const float* __restrict__ bir, const float* __restrict__ bz)
{
    int m0 = blockIdx.x * 64, n0 = blockIdx.y * 128, jj = blockIdx.z;
    const __half* A = g_zcat + (size_t)m0 * 2 * Cc + (jj == 1 ? Cc : 0);
    int Kd = (jj == 2) ? 2 * Cc : Cc;
    const __half* W    = (jj == 2) ? (g_wh + 524288) : (g_wh + (6 + jj) * 65536);
    const float* bias = (jj == 0) ? brgb : ((jj == 1) ? bir : bz);
    float acc[2][8][4] = {};
    gemm64_fp16(A, 2 * Cc, W + (size_t)n0 * Kd, Kd, Kd, acc);

    const int tid = threadIdx.x, lane = tid & 31, warp = tid >> 5;
    const int wm = (warp >> 1) * 32, wn = (warp & 1) * 64;
    const int g = lane >> 2, tg = lane & 3;
    float* out = g_pre[jj] + (size_t)m0 * Cc + n0;
#pragma unroll
    for (int mi = 0; mi < 2; mi++) {
        int r0 = wm + mi * 16 + g;
#pragma unroll
        for (int ni = 0; ni < 8; ni++) {
            int col = wn + ni * 8 + 2 * tg;
            float b0 = bias[n0 + col], b1 = bias[n0 + col + 1];
            float2 v0 = { acc[mi][ni][0] + b0, acc[mi][ni][1] + b1 };
            float2 v1 = { acc[mi][ni][2] + b0, acc[mi][ni][3] + b1 };
            *(float2*)(out + (size_t)r0 * Cc + col) = v0;
            *(float2*)(out + (size_t)(r0 + 8) * Cc + col) = v1;
        }
    }
}

// ---------------- gate fuse + smem transpose to [B,C,N] ----------------
__global__ void fuse_kernel(const int* __restrict__ time_idx, const float* __restrict__ temb) {
    __shared__ float t[32][33];
    int b = blockIdx.z;
    int n0 = blockIdx.x * 32, c0 = blockIdx.y * 32;
    int tx = threadIdx.x, ty = threadIdx.y;
    int ti = time_idx[b];
#pragma unroll
    for (int i = 0; i < 4; i++) {
        int n = n0 + ty + 8 * i, c = c0 + tx;
        size_t m = ((size_t)b * NT + n) * Cc + c;
        float hr = tanhf(g_pre[0][m]);
        float hi = tanhf(g_pre[1][m]);
        float zb = 1.0f / (1.0f + __expf(-g_pre[2][m]));
        float te = temb[ti * Cc + c];
        float zf = 1.0f / (1.0f + __expf(-(zb + te)));
        t[ty + 8 * i][tx] = zf * hr + (1.0f - zf) * hi;
    }
    __syncthreads();
#pragma unroll
    for (int i = 0; i < 4; i++) {
        int c = c0 + ty + 8 * i, n = n0 + tx;
        g_fused[((size_t)b * Cc + c) * NT + n] = t[tx][ty + 8 * i];
    }
}

// ---------------- bilinear upsample 40 -> 160 ----------------
__global__ void upsample_kernel(float* __restrict__ out) {
    int idx = blockIdx.x * blockDim.x + threadIdx.x;
    if (idx >= Bb*Cc*HH*WW) return;
    int w  = idx % WW;
    int h  = (idx / WW) % HH;
    int bc = idx / (HH * WW);
    float sh = fmaxf(h * 0.25f - 0.375f, 0.0f);
    float sw = fmaxf(w * 0.25f - 0.375f, 0.0f);
    int h0 = (int)sh; float fh = sh - (float)h0; int h1 = min(h0 + 1, HDs - 1);
    int w0 = (int)sw; float fw = sw - (float)w0; int w1 = min(w0 + 1, WDs - 1);
    const float* p = g_fused + (size_t)bc * NT;
    float v00 = p[h0 * WDs + w0], v01 = p[h0 * WDs + w1];
    float v10 = p[h1 * WDs + w0], v11 = p[h1 * WDs + w1];
    float top = v00 * (1.0f - fw) + v01 * fw;
    float bot = v10 * (1.0f - fw) + v11 * fw;
    out[idx] = top * (1.0f - fh) + bot * fh;
}

extern "C" void kernel_launch(void* const* d_in, const int* in_sizes, int n_in,
                              void* d_out, int out_size) {
    const float* z_rgb  = (const float*)d_in[0];
    const float* z_ir   = (const float*)d_in[1];
    const int*   tidx   = (const int*)  d_in[2];
    const float* Wq_rgb = (const float*)d_in[3],  *bq_rgb = (const float*)d_in[4];
    const float* Wk_ir  = (const float*)d_in[5],  *bk_ir  = (const float*)d_in[6];
    const float* Wv_ir  = (const float*)d_in[7],  *bv_ir  = (const float*)d_in[8];
    const float* Wq_ir  = (const float*)d_in[9],  *bq_ir  = (const float*)d_in[10];
    const float* Wk_rgb = (const float*)d_in[11], *bk_rgb = (const float*)d_in[12];
    const float* Wv_rgb = (const float*)d_in[13], *bv_rgb = (const float*)d_in[14];
    const float* Wrgb   = (const float*)d_in[15], *brgb   = (const float*)d_in[16];
    const float* Wir    = (const float*)d_in[17], *bir    = (const float*)d_in[18];
    const float* Wz     = (const float*)d_in[19], *bz     = (const float*)d_in[20];
    const float* temb   = (const float*)d_in[21];

    static bool attr_done = false;
    if (!attr_done) {
        cudaFuncSetAttribute(fattn_kernel, cudaFuncAttributeMaxDynamicSharedMemorySize, FATTN_SMEM);
        attr_done = true;
    }

    wprep_kernel<<<dim3(512, 9), 256>>>(Wq_rgb, Wk_ir, Wv_ir, Wq_ir, Wk_rgb, Wv_rgb,
                                        Wrgb, Wir, Wz);
    ds_kernel<<<dim3(50, 8, 8), dim3(32, 8)>>>(z_rgb, z_ir);
    proj_gemm<<<dim3(200, 2, 6), 128>>>(bq_rgb, bk_ir, bv_ir, bq_ir, bk_rgb, bv_rgb);
    fattn_kernel<<<dim3(50, 16), 128, FATTN_SMEM>>>();
    final_gemm<<<dim3(200, 2, 3), 128>>>(brgb, bir, bz);
    fuse_kernel<<<dim3(NT/32, Cc/32, Bb), dim3(32, 8)>>>(tidx, temb);
    upsample_kernel<<<(Bb*Cc*HH*WW + 255) / 256, 256>>>((float*)d_out);
}